// round 2
// baseline (speedup 1.0000x reference)
#include <cuda_runtime.h>

// Problem constants
#define NB    32
#define CIN   128
#define COUT  256
#define HH    56
#define WW    56
#define HWSZ  (HH*WW)          // 3136
#define KTOT  (9*CIN)          // 1152, K ordered as (kh*3+kw)*128 + ci
#define PTOT  (NB*HWSZ)        // 100352

// GEMM tiling
#define BM 128
#define BN 128
#define BK 8
#define TM 8
#define TN 8
#define NTILES (KTOT/BK)       // 144

// Scratch: weights reordered k-major, Wr[k*COUT + co], k = (r*3+s)*128 + ci
__device__ float g_Wr[KTOT * COUT];

__global__ void reorder_weights_kernel(const float* __restrict__ w) {
    int idx = blockIdx.x * blockDim.x + threadIdx.x;
    if (idx >= KTOT * COUT) return;
    int co = idx % COUT;
    int k  = idx / COUT;
    int rs = k >> 7;           // kh*3+kw  (0..8)
    int ci = k & 127;
    // w is [COUT][CIN][3][3] row-major: w[co*1152 + ci*9 + rs]
    g_Wr[idx] = w[co * (CIN * 9) + ci * 9 + rs];
}

__global__ __launch_bounds__(256, 2)
void conv_igemm_kernel(const float* __restrict__ x,
                       const float* __restrict__ bias,
                       float* __restrict__ out) {
    __shared__ float As[2][BK][BM];
    __shared__ float Bs[2][BK][BN];

    const int t  = threadIdx.x;
    const int bm = blockIdx.y;   // 0..1   (C_out tile)
    const int bn = blockIdx.x;   // 0..783 (pixel tile)

    // ---- B (im2col) load assignment: col = t&127, 4 consecutive k-rows ----
    const int b_col = t & 127;
    const int b_rb  = (t >> 7) * 4;          // 0 or 4
    const int p  = bn * BN + b_col;
    const int n  = p / HWSZ;
    const int hw = p - n * HWSZ;
    const int h  = hw / WW;
    const int w  = hw - h * WW;
    const float* __restrict__ xn = x + n * (CIN * HWSZ);

    // ---- A load assignment: float4 flat over the 8x128 tile ----
    const int a_row = t >> 5;                // 0..7 (k within tile)
    const int a_col = (t & 31) << 2;         // 0..124 (co within tile)

    const int tx = t & 15;
    const int ty = t >> 4;

    float acc[TM][TN];
#pragma unroll
    for (int i = 0; i < TM; i++)
#pragma unroll
        for (int j = 0; j < TN; j++) acc[i][j] = 0.f;

    // ---- prologue: load tile 0 into buffer 0 ----
    {
        const int k0 = 0;
        float4 a = *reinterpret_cast<const float4*>(
            g_Wr + (k0 + a_row) * COUT + bm * BM + a_col);
        *reinterpret_cast<float4*>(&As[0][a_row][a_col]) = a;

        const int rs = k0 >> 7;              // 0
        const int r = rs / 3, s = rs % 3;
        const int ih = h + r - 1, iw = w + s - 1;
        const bool valid = ((unsigned)ih < HH) && ((unsigned)iw < WW);
        const int off = ih * WW + iw;
        const int ci0 = k0 & 127;
#pragma unroll
        for (int j = 0; j < 4; j++) {
            const int ci = ci0 + b_rb + j;
            Bs[0][b_rb + j][b_col] = valid ? xn[ci * HWSZ + off] : 0.f;
        }
    }
    __syncthreads();

    int buf = 0;
#pragma unroll 1
    for (int kt = 0; kt < NTILES; kt++) {
        // ---- prefetch next tile into registers ----
        float4 a_n;
        float  b_n[4];
        const bool have_next = (kt + 1 < NTILES);
        if (have_next) {
            const int k0 = (kt + 1) * BK;
            a_n = *reinterpret_cast<const float4*>(
                g_Wr + (k0 + a_row) * COUT + bm * BM + a_col);

            const int rs = k0 >> 7;
            const int r = rs / 3, s = rs % 3;
            const int ih = h + r - 1, iw = w + s - 1;
            const bool valid = ((unsigned)ih < HH) && ((unsigned)iw < WW);
            const int off = ih * WW + iw;
            const int ci0 = k0 & 127;
#pragma unroll
            for (int j = 0; j < 4; j++) {
                const int ci = ci0 + b_rb + j;
                b_n[j] = valid ? xn[ci * HWSZ + off] : 0.f;
            }
        }

        // ---- compute on current buffer ----
#pragma unroll
        for (int kk = 0; kk < BK; kk++) {
            float4 a0 = *reinterpret_cast<const float4*>(&As[buf][kk][ty * TM]);
            float4 a1 = *reinterpret_cast<const float4*>(&As[buf][kk][ty * TM + 4]);
            float4 b0 = *reinterpret_cast<const float4*>(&Bs[buf][kk][tx * TN]);
            float4 b1 = *reinterpret_cast<const float4*>(&Bs[buf][kk][tx * TN + 4]);
            float av[TM] = {a0.x, a0.y, a0.z, a0.w, a1.x, a1.y, a1.z, a1.w};
            float bv[TN] = {b0.x, b0.y, b0.z, b0.w, b1.x, b1.y, b1.z, b1.w};
#pragma unroll
            for (int i = 0; i < TM; i++)
#pragma unroll
                for (int j = 0; j < TN; j++)
                    acc[i][j] += av[i] * bv[j];
        }

        // ---- stage next tile into the other buffer ----
        if (have_next) {
            const int nb = buf ^ 1;
            *reinterpret_cast<float4*>(&As[nb][a_row][a_col]) = a_n;
#pragma unroll
            for (int j = 0; j < 4; j++)
                Bs[nb][b_rb + j][b_col] = b_n[j];
        }
        __syncthreads();
        buf ^= 1;
    }

    // ---- epilogue: bias + scatter to NCHW output ----
    float bv[TM];
#pragma unroll
    for (int i = 0; i < TM; i++)
        bv[i] = __ldg(bias + bm * BM + ty * TM + i);

#pragma unroll
    for (int j = 0; j < TN; j++) {
        const int pj  = bn * BN + tx * TN + j;
        const int nj  = pj / HWSZ;
        const int hwj = pj - nj * HWSZ;
        float* __restrict__ outp = out + (size_t)nj * (COUT * HWSZ) + hwj;
        const int co0 = bm * BM + ty * TM;
#pragma unroll
        for (int i = 0; i < TM; i++) {
            outp[(co0 + i) * HWSZ] = acc[i][j] + bv[i];
        }
    }
}

extern "C" void kernel_launch(void* const* d_in, const int* in_sizes, int n_in,
                              void* d_out, int out_size) {
    const float* x    = (const float*)d_in[0];
    const float* wgt  = (const float*)d_in[1];
    const float* bias = (const float*)d_in[2];
    float* out        = (float*)d_out;

    reorder_weights_kernel<<<(KTOT * COUT + 255) / 256, 256>>>(wgt);

    dim3 grid(PTOT / BN, COUT / BM);   // (784, 2)
    conv_igemm_kernel<<<grid, 256>>>(x, bias, out);
}

// round 9
// speedup vs baseline: 1.9215x; 1.9215x over previous
#include <cuda_runtime.h>
#include <cuda_bf16.h>
#include <cstdint>

// ---------------- problem constants ----------------
#define NB    32
#define CIN   128
#define COUT  256
#define HH    56
#define WW    56
#define HWSZ  3136
#define PTOT  100352
#define KTOT  1152

// ---------------- tiling ----------------
#define BM 128          // cout per CTA
#define BN 128          // pixels per CTA
#define BKC 32          // channels per stage
#define NST 36          // 1152/32
#define STAGES 6
#define STAGE_BYTES 32768           // A 16KB + B 16KB
#define B_OFF 16384
#define SMEM_TOTAL (STAGES*STAGE_BYTES)   // 196608

// ---------------- scratch ----------------
// x transposed to [n][hw][ci], split hi/lo bf16
__device__ __nv_bfloat16 g_Xth[(size_t)NB * HWSZ * CIN];
__device__ __nv_bfloat16 g_Xtl[(size_t)NB * HWSZ * CIN];
// weights packed [co][stage kt][64] = [hi ch0..31 | lo ch0..31]
__device__ __nv_bfloat16 g_Wp[(size_t)COUT * NST * 64];

__device__ __forceinline__ uint32_t swz(uint32_t o) { return o ^ ((o >> 3) & 0x70); }

__device__ __forceinline__ uint32_t s2u(const void* p) {
    uint32_t a;
    asm("{ .reg .u64 t; cvta.to.shared.u64 t, %1; cvt.u32.u64 %0, t; }" : "=r"(a) : "l"(p));
    return a;
}

#define CP16(dst, src, sz) \
    asm volatile("cp.async.cg.shared.global [%0], [%1], 16, %2;" \
                 :: "r"(dst), "l"(src), "r"(sz) : "memory")
#define CP_COMMIT() asm volatile("cp.async.commit_group;" ::: "memory")
#define CP_WAIT(n)  asm volatile("cp.async.wait_group %0;" :: "n"(n) : "memory")

__device__ __forceinline__ void ldsm4(uint32_t* r, uint32_t addr) {
    asm volatile("ldmatrix.sync.aligned.m8n8.x4.shared.b16 {%0,%1,%2,%3}, [%4];"
        : "=r"(r[0]), "=r"(r[1]), "=r"(r[2]), "=r"(r[3]) : "r"(addr));
}

__device__ __forceinline__ void mma16816(float* d, const uint32_t* a, const uint32_t* b) {
    asm volatile("mma.sync.aligned.m16n8k16.row.col.f32.bf16.bf16.f32 "
        "{%0,%1,%2,%3}, {%4,%5,%6,%7}, {%8,%9}, {%0,%1,%2,%3};"
        : "+f"(d[0]), "+f"(d[1]), "+f"(d[2]), "+f"(d[3])
        : "r"(a[0]), "r"(a[1]), "r"(a[2]), "r"(a[3]), "r"(b[0]), "r"(b[1]));
}

// ---------------- prologue: transpose + split x ----------------
__global__ void prep_x(const float* __restrict__ x) {
    __shared__ float tile[32][33];
    const int n = blockIdx.z, cb = blockIdx.y, hb = blockIdx.x;
    const int t = threadIdx.x;
    const int tr = t >> 5, tc = t & 31;
    const float* xp = x + ((size_t)(n * CIN + cb * 32)) * HWSZ + hb * 32;
#pragma unroll
    for (int i = 0; i < 4; i++)
        tile[tr + i * 8][tc] = xp[(size_t)(tr + i * 8) * HWSZ + tc];
    __syncthreads();
#pragma unroll
    for (int it = 0; it < 2; it++) {
        const int idx = it * 256 + t;
        const int hwl = idx >> 4, cp = idx & 15;
        const float v0 = tile[cp * 2][hwl];
        const float v1 = tile[cp * 2 + 1][hwl];
        const __nv_bfloat16 h0 = __float2bfloat16(v0);
        const __nv_bfloat16 h1 = __float2bfloat16(v1);
        const __nv_bfloat16 l0 = __float2bfloat16(v0 - __bfloat162float(h0));
        const __nv_bfloat16 l1 = __float2bfloat16(v1 - __bfloat162float(h1));
        const uint32_t hp = (uint32_t)__bfloat16_as_ushort(h0) |
                            ((uint32_t)__bfloat16_as_ushort(h1) << 16);
        const uint32_t lp = (uint32_t)__bfloat16_as_ushort(l0) |
                            ((uint32_t)__bfloat16_as_ushort(l1) << 16);
        const size_t e = ((size_t)(n * HWSZ + hb * 32 + hwl)) * CIN + cb * 32 + cp * 2;
        *reinterpret_cast<uint32_t*>(&g_Xth[e]) = hp;
        *reinterpret_cast<uint32_t*>(&g_Xtl[e]) = lp;
    }
}

// ---------------- prologue: pack + split weights ----------------
__global__ void prep_w(const float* __restrict__ w) {
    const int idx = blockIdx.x * blockDim.x + threadIdx.x;
    if (idx >= COUT * NST * 64) return;
    const int co = idx / (NST * 64);
    const int r2 = idx - co * (NST * 64);
    const int kt = r2 >> 6;
    const int j  = r2 & 63;
    const int k  = kt * BKC + (j & 31);
    const int rs = k >> 7;
    const int ci = k & 127;
    const float v = w[co * (CIN * 9) + ci * 9 + rs];
    const __nv_bfloat16 h = __float2bfloat16(v);
    g_Wp[idx] = (j < 32) ? h : __float2bfloat16(v - __bfloat162float(h));
}

// ---------------- main kernel ----------------
__global__ __launch_bounds__(256, 1)
void conv_mma_kernel(const float* __restrict__ bias, float* __restrict__ out) {
    extern __shared__ char smem[];
    const uint32_t sb = s2u(smem);
    const int t = threadIdx.x, lane = t & 31, warp = t >> 5;
    const int bn = blockIdx.x, bm = blockIdx.y;

    // ---- loader roles: 2 threads per row, quad 0 = hi half, 1 = lo half ----
    const int lrow = t & 127, quad = t >> 7;
    const __nv_bfloat16* a_src =
        g_Wp + (size_t)(bm * BM + lrow) * (NST * 64) + quad * 32;
    uint32_t ldst[4];
#pragma unroll
    for (int c = 0; c < 4; c++)
        ldst[c] = swz((uint32_t)(lrow * 128 + quad * 64 + c * 16));

    const int p    = bn * BN + lrow;
    const int nimg = p / HWSZ;
    const int hw   = p - nimg * HWSZ;
    const int ph   = hw / WW, pw = hw - ph * WW;
    const __nv_bfloat16* xbase =
        (quad ? g_Xtl : g_Xth) + (size_t)nimg * HWSZ * CIN;

    auto load_stage = [&](int kt) {
        const uint32_t base = sb + (uint32_t)(kt % STAGES) * STAGE_BYTES;
        const __nv_bfloat16* as = a_src + (size_t)kt * 64;
#pragma unroll
        for (int c = 0; c < 4; c++)
            CP16(base + ldst[c], as + c * 8, 16);
        const int rs = kt >> 2;
        const int r  = rs / 3, s = rs - 3 * (rs / 3);
        const int ih = ph + r - 1, iw = pw + s - 1;
        const bool valid = ((unsigned)ih < HH) && ((unsigned)iw < WW);
        const int sz  = valid ? 16 : 0;
        const int off = valid ? (ih * WW + iw) : 0;
        const __nv_bfloat16* bs = xbase + (size_t)off * CIN + (kt & 3) * 32;
#pragma unroll
        for (int c = 0; c < 4; c++)
            CP16(base + B_OFF + ldst[c], bs + c * 8, sz);
        CP_COMMIT();
    };

    // ---- MMA roles: 8 warps, 4x2 over (M,N); warp tile 32x64 ----
    const int m0 = (warp >> 1) * 32;
    const int n0 = (warp & 1) * 64;
    const int arow_l = lane & 15;
    const int abyte  = lane & 16;                       // 0/16
    const int brow_l = ((lane & 16) >> 1) + (lane & 7); // n row within 16-tile
    const int bbyte  = (lane & 8) * 2;                  // 0/16

    float acc[2][8][4];
#pragma unroll
    for (int i = 0; i < 2; i++)
#pragma unroll
        for (int j = 0; j < 8; j++)
#pragma unroll
            for (int q = 0; q < 4; q++) acc[i][j][q] = 0.f;

    for (int kt = 0; kt < STAGES - 1; kt++) load_stage(kt);   // 5 groups

#pragma unroll 1
    for (int kt = 0; kt < NST; kt++) {
        CP_WAIT(4);
        __syncthreads();
        if (kt + STAGES - 1 < NST) load_stage(kt + STAGES - 1);
        else                       CP_COMMIT();   // keep group arithmetic constant

        const uint32_t base = sb + (uint32_t)(kt % STAGES) * STAGE_BYTES;
#pragma unroll
        for (int ks = 0; ks < 2; ks++) {
            uint32_t Ah[2][4], Al[2][4], Bh[4][4], Bl[4][4];
#pragma unroll
            for (int mi = 0; mi < 2; mi++) {
                const uint32_t rowb = (uint32_t)((m0 + mi * 16 + arow_l) * 128);
                ldsm4(Ah[mi], base + swz(rowb + ks * 32 + abyte));
                ldsm4(Al[mi], base + swz(rowb + 64 + ks * 32 + abyte));
            }
#pragma unroll
            for (int nj = 0; nj < 4; nj++) {
                const uint32_t rowb = (uint32_t)((n0 + nj * 16 + brow_l) * 128);
                ldsm4(Bh[nj], base + B_OFF + swz(rowb + ks * 32 + bbyte));
                ldsm4(Bl[nj], base + B_OFF + swz(rowb + 64 + ks * 32 + bbyte));
            }
#pragma unroll
            for (int mi = 0; mi < 2; mi++)
#pragma unroll
                for (int nj = 0; nj < 8; nj++) {
                    const uint32_t* bh = &Bh[nj >> 1][(nj & 1) * 2];
                    const uint32_t* bl = &Bl[nj >> 1][(nj & 1) * 2];
                    mma16816(acc[mi][nj], Ah[mi], bh);   // hi*hi
                    mma16816(acc[mi][nj], Ah[mi], bl);   // hi*lo
                    mma16816(acc[mi][nj], Al[mi], bh);   // lo*hi
                }
        }
    }

    // ---- epilogue: bias + direct STG.64 to NCHW ----
    float bv[2][2];
#pragma unroll
    for (int mi = 0; mi < 2; mi++)
#pragma unroll
        for (int hf = 0; hf < 2; hf++)
            bv[mi][hf] = __ldg(bias + bm * BM + m0 + mi * 16 + (lane >> 2) + hf * 8);

#pragma unroll
    for (int nj = 0; nj < 8; nj++) {
        const int pp  = bn * BN + n0 + nj * 8 + (lane & 3) * 2;
        const int n2  = pp / HWSZ;
        const int hw2 = pp - n2 * HWSZ;
        float* op = out + ((size_t)n2 * COUT + bm * BM) * HWSZ + hw2;
#pragma unroll
        for (int mi = 0; mi < 2; mi++) {
            const int mr = m0 + mi * 16 + (lane >> 2);
            float2 v0 = make_float2(acc[mi][nj][0] + bv[mi][0],
                                    acc[mi][nj][1] + bv[mi][0]);
            float2 v1 = make_float2(acc[mi][nj][2] + bv[mi][1],
                                    acc[mi][nj][3] + bv[mi][1]);
            *reinterpret_cast<float2*>(op + (size_t)mr * HWSZ)       = v0;
            *reinterpret_cast<float2*>(op + (size_t)(mr + 8) * HWSZ) = v1;
        }
    }
}

extern "C" void kernel_launch(void* const* d_in, const int* in_sizes, int n_in,
                              void* d_out, int out_size) {
    const float* x    = (const float*)d_in[0];
    const float* wgt  = (const float*)d_in[1];
    const float* bias = (const float*)d_in[2];
    float* out        = (float*)d_out;

    cudaFuncSetAttribute(conv_mma_kernel,
                         cudaFuncAttributeMaxDynamicSharedMemorySize, SMEM_TOTAL);

    prep_x<<<dim3(HWSZ / 32, CIN / 32, NB), 256>>>(x);
    prep_w<<<(COUT * NST * 64 + 255) / 256, 256>>>(wgt);

    dim3 grid(PTOT / BN, COUT / BM);   // (784, 2)
    conv_mma_kernel<<<grid, 256, SMEM_TOTAL>>>(bias, out);
}

// round 12
// speedup vs baseline: 2.0645x; 1.0744x over previous
#include <cuda_runtime.h>
#include <cuda_bf16.h>
#include <cstdint>

// ---------------- problem constants ----------------
#define NB    32
#define CIN   128
#define COUT  256
#define HH    56
#define WW    56
#define HWSZ  3136
#define PTOT  100352
#define KTOT  1152

// ---------------- tiling ----------------
#define BM 128          // cout per CTA
#define BN 128          // pixels per CTA
#define BKC 32          // channels per stage
#define NST 36          // 1152/32
#define STAGES 3
#define STAGE_BYTES 32768           // A 16KB + B 16KB
#define B_OFF 16384
#define SMEM_TOTAL (STAGES*STAGE_BYTES)   // 98304 -> 2 CTAs/SM

// ---------------- scratch ----------------
__device__ __nv_bfloat16 g_Xth[(size_t)NB * HWSZ * CIN];
__device__ __nv_bfloat16 g_Xtl[(size_t)NB * HWSZ * CIN];
__device__ __nv_bfloat16 g_Wp[(size_t)COUT * NST * 64];

__device__ __forceinline__ uint32_t swz(uint32_t o) { return o ^ ((o >> 3) & 0x70); }

__device__ __forceinline__ uint32_t s2u(const void* p) {
    uint32_t a;
    asm("{ .reg .u64 t; cvta.to.shared.u64 t, %1; cvt.u32.u64 %0, t; }" : "=r"(a) : "l"(p));
    return a;
}

#define CP16(dst, src, sz) \
    asm volatile("cp.async.cg.shared.global [%0], [%1], 16, %2;" \
                 :: "r"(dst), "l"(src), "r"(sz) : "memory")
#define CP_COMMIT() asm volatile("cp.async.commit_group;" ::: "memory")
#define CP_WAIT(n)  asm volatile("cp.async.wait_group %0;" :: "n"(n) : "memory")

__device__ __forceinline__ void ldsm4(uint32_t* r, uint32_t addr) {
    asm volatile("ldmatrix.sync.aligned.m8n8.x4.shared.b16 {%0,%1,%2,%3}, [%4];"
        : "=r"(r[0]), "=r"(r[1]), "=r"(r[2]), "=r"(r[3]) : "r"(addr));
}

__device__ __forceinline__ void mma16816(float* d, const uint32_t* a, const uint32_t* b) {
    asm volatile("mma.sync.aligned.m16n8k16.row.col.f32.bf16.bf16.f32 "
        "{%0,%1,%2,%3}, {%4,%5,%6,%7}, {%8,%9}, {%0,%1,%2,%3};"
        : "+f"(d[0]), "+f"(d[1]), "+f"(d[2]), "+f"(d[3])
        : "r"(a[0]), "r"(a[1]), "r"(a[2]), "r"(a[3]), "r"(b[0]), "r"(b[1]));
}

// ---------------- prologue: transpose + split x ----------------
__global__ void prep_x(const float* __restrict__ x) {
    __shared__ float tile[32][33];
    const int n = blockIdx.z, cb = blockIdx.y, hb = blockIdx.x;
    const int t = threadIdx.x;
    const int tr = t >> 5, tc = t & 31;
    const float* xp = x + ((size_t)(n * CIN + cb * 32)) * HWSZ + hb * 32;
#pragma unroll
    for (int i = 0; i < 4; i++)
        tile[tr + i * 8][tc] = xp[(size_t)(tr + i * 8) * HWSZ + tc];
    __syncthreads();
#pragma unroll
    for (int it = 0; it < 2; it++) {
        const int idx = it * 256 + t;
        const int hwl = idx >> 4, cp = idx & 15;
        const float v0 = tile[cp * 2][hwl];
        const float v1 = tile[cp * 2 + 1][hwl];
        const __nv_bfloat16 h0 = __float2bfloat16(v0);
        const __nv_bfloat16 h1 = __float2bfloat16(v1);
        const __nv_bfloat16 l0 = __float2bfloat16(v0 - __bfloat162float(h0));
        const __nv_bfloat16 l1 = __float2bfloat16(v1 - __bfloat162float(h1));
        const uint32_t hp = (uint32_t)__bfloat16_as_ushort(h0) |
                            ((uint32_t)__bfloat16_as_ushort(h1) << 16);
        const uint32_t lp = (uint32_t)__bfloat16_as_ushort(l0) |
                            ((uint32_t)__bfloat16_as_ushort(l1) << 16);
        const size_t e = ((size_t)(n * HWSZ + hb * 32 + hwl)) * CIN + cb * 32 + cp * 2;
        *reinterpret_cast<uint32_t*>(&g_Xth[e]) = hp;
        *reinterpret_cast<uint32_t*>(&g_Xtl[e]) = lp;
    }
}

// ---------------- prologue: pack + split weights ----------------
__global__ void prep_w(const float* __restrict__ w) {
    const int idx = blockIdx.x * blockDim.x + threadIdx.x;
    if (idx >= COUT * NST * 64) return;
    const int co = idx / (NST * 64);
    const int r2 = idx - co * (NST * 64);
    const int kt = r2 >> 6;
    const int j  = r2 & 63;
    const int k  = kt * BKC + (j & 31);
    const int rs = k >> 7;
    const int ci = k & 127;
    const float v = w[co * (CIN * 9) + ci * 9 + rs];
    const __nv_bfloat16 h = __float2bfloat16(v);
    g_Wp[idx] = (j < 32) ? h : __float2bfloat16(v - __bfloat162float(h));
}

// ---------------- main kernel ----------------
__global__ __launch_bounds__(256, 2)
void conv_mma_kernel(const float* __restrict__ bias, float* __restrict__ out) {
    extern __shared__ char smem[];
    const uint32_t sb = s2u(smem);
    const int t = threadIdx.x, lane = t & 31, warp = t >> 5;
    const int bn = blockIdx.x, bm = blockIdx.y;

    // ---- loader roles: 2 threads per row, quad 0 = hi half, 1 = lo half ----
    const int lrow = t & 127, quad = t >> 7;
    const __nv_bfloat16* a_src =
        g_Wp + (size_t)(bm * BM + lrow) * (NST * 64) + quad * 32;
    uint32_t ldst[4];
#pragma unroll
    for (int c = 0; c < 4; c++)
        ldst[c] = swz((uint32_t)(lrow * 128 + quad * 64 + c * 16));

    const int p    = bn * BN + lrow;
    const int nimg = p / HWSZ;
    const int hw   = p - nimg * HWSZ;
    const int ph   = hw / WW, pw = hw - ph * WW;
    const __nv_bfloat16* xbase =
        (quad ? g_Xtl : g_Xth) + (size_t)nimg * HWSZ * CIN;

    auto load_stage = [&](int kt) {
        const uint32_t base = sb + (uint32_t)(kt % STAGES) * STAGE_BYTES;
        const __nv_bfloat16* as = a_src + (size_t)kt * 64;
#pragma unroll
        for (int c = 0; c < 4; c++)
            CP16(base + ldst[c], as + c * 8, 16);
        const int rs = kt >> 2;
        const int r  = rs / 3, s = rs - 3 * (rs / 3);
        const int ih = ph + r - 1, iw = pw + s - 1;
        const bool valid = ((unsigned)ih < HH) && ((unsigned)iw < WW);
        const int sz  = valid ? 16 : 0;
        const int off = valid ? (ih * WW + iw) : 0;
        const __nv_bfloat16* bs = xbase + (size_t)off * CIN + (kt & 3) * 32;
#pragma unroll
        for (int c = 0; c < 4; c++)
            CP16(base + B_OFF + ldst[c], bs + c * 8, sz);
        CP_COMMIT();
    };

    // ---- MMA roles: 8 warps, 4x2 over (M,N); warp tile 32x64 ----
    const int m0 = (warp >> 1) * 32;
    const int n0 = (warp & 1) * 64;
    const int arow_l = lane & 15;
    const int abyte  = lane & 16;
    const int brow_l = ((lane & 16) >> 1) + (lane & 7);
    const int bbyte  = (lane & 8) * 2;

    float acc[2][8][4];
#pragma unroll
    for (int i = 0; i < 2; i++)
#pragma unroll
        for (int j = 0; j < 8; j++)
#pragma unroll
            for (int q = 0; q < 4; q++) acc[i][j][q] = 0.f;

    for (int kt = 0; kt < STAGES - 1; kt++) load_stage(kt);   // 2 groups

#pragma unroll 1
    for (int kt = 0; kt < NST; kt++) {
        CP_WAIT(1);
        __syncthreads();
        if (kt + STAGES - 1 < NST) load_stage(kt + STAGES - 1);
        else                       CP_COMMIT();   // keep group count constant

        const uint32_t base = sb + (uint32_t)(kt % STAGES) * STAGE_BYTES;
#pragma unroll
        for (int ks = 0; ks < 2; ks++) {
            uint32_t Ah[2][4], Al[2][4];
#pragma unroll
            for (int mi = 0; mi < 2; mi++) {
                const uint32_t rowb = (uint32_t)((m0 + mi * 16 + arow_l) * 128);
                ldsm4(Ah[mi], base + swz(rowb + ks * 32 + abyte));
                ldsm4(Al[mi], base + swz(rowb + 64 + ks * 32 + abyte));
            }
            // consume B fragments immediately -> small live set (fits 128 regs)
#pragma unroll
            for (int nj4 = 0; nj4 < 4; nj4++) {
                uint32_t Bh[4], Bl[4];
                const uint32_t rowb = (uint32_t)((n0 + nj4 * 16 + brow_l) * 128);
                ldsm4(Bh, base + B_OFF + swz(rowb + ks * 32 + bbyte));
                ldsm4(Bl, base + B_OFF + swz(rowb + 64 + ks * 32 + bbyte));
#pragma unroll
                for (int mi = 0; mi < 2; mi++) {
#pragma unroll
                    for (int half = 0; half < 2; half++) {
                        float* a0 = acc[mi][nj4 * 2 + half];
                        mma16816(a0, Ah[mi], &Bh[half * 2]);   // hi*hi
                        mma16816(a0, Ah[mi], &Bl[half * 2]);   // hi*lo
                        mma16816(a0, Al[mi], &Bh[half * 2]);   // lo*hi
                    }
                }
            }
        }
    }

    // ---- epilogue: bias + direct STG.64 to NCHW ----
    float bv[2][2];
#pragma unroll
    for (int mi = 0; mi < 2; mi++)
#pragma unroll
        for (int hf = 0; hf < 2; hf++)
            bv[mi][hf] = __ldg(bias + bm * BM + m0 + mi * 16 + (lane >> 2) + hf * 8);

#pragma unroll
    for (int nj = 0; nj < 8; nj++) {
        const int pp  = bn * BN + n0 + nj * 8 + (lane & 3) * 2;
        const int n2  = pp / HWSZ;
        const int hw2 = pp - n2 * HWSZ;
        float* op = out + ((size_t)n2 * COUT + bm * BM) * HWSZ + hw2;
#pragma unroll
        for (int mi = 0; mi < 2; mi++) {
            const int mr = m0 + mi * 16 + (lane >> 2);
            float2 v0 = make_float2(acc[mi][nj][0] + bv[mi][0],
                                    acc[mi][nj][1] + bv[mi][0]);
            float2 v1 = make_float2(acc[mi][nj][2] + bv[mi][1],
                                    acc[mi][nj][3] + bv[mi][1]);
            *reinterpret_cast<float2*>(op + (size_t)mr * HWSZ)       = v0;
            *reinterpret_cast<float2*>(op + (size_t)(mr + 8) * HWSZ) = v1;
        }
    }
}

extern "C" void kernel_launch(void* const* d_in, const int* in_sizes, int n_in,
                              void* d_out, int out_size) {
    const float* x    = (const float*)d_in[0];
    const float* wgt  = (const float*)d_in[1];
    const float* bias = (const float*)d_in[2];
    float* out        = (float*)d_out;

    cudaFuncSetAttribute(conv_mma_kernel,
                         cudaFuncAttributeMaxDynamicSharedMemorySize, SMEM_TOTAL);

    prep_x<<<dim3(HWSZ / 32, CIN / 32, NB), 256>>>(x);
    prep_w<<<(COUT * NST * 64 + 255) / 256, 256>>>(wgt);

    dim3 grid(PTOT / BN, COUT / BM);   // (784, 2)
    conv_mma_kernel<<<grid, 256, SMEM_TOTAL>>>(bias, out);
}

// round 14
// speedup vs baseline: 4.6742x; 2.2641x over previous
#include <cuda_runtime.h>
#include <cuda_fp16.h>
#include <cstdint>

// ---------------- problem constants ----------------
#define NB    32
#define CIN   128
#define COUT  256
#define HH    56
#define WW    56
#define HWSZ  3136
#define PTOT  100352
#define KTOT  1152

// ---------------- tiling ----------------
#define BM 128          // cout per CTA
#define BN 128          // pixels per CTA
#define BKC 64          // channels per stage (fp16, 128B rows)
#define NST 18          // 1152/64
#define STAGES 3
#define STAGE_BYTES 32768           // A 16KB + B 16KB
#define B_OFF 16384
#define SMEM_TOTAL (STAGES*STAGE_BYTES)   // 98304 -> 2 CTAs/SM

// ---------------- scratch ----------------
__device__ __half g_Xh[(size_t)NB * HWSZ * CIN];        // x transposed [n][hw][ci], fp16
__device__ __half g_Wp[(size_t)COUT * KTOT];            // w packed [co][k], fp16

__device__ __forceinline__ uint32_t swz(uint32_t o) { return o ^ ((o >> 3) & 0x70); }

__device__ __forceinline__ uint32_t s2u(const void* p) {
    uint32_t a;
    asm("{ .reg .u64 t; cvta.to.shared.u64 t, %1; cvt.u32.u64 %0, t; }" : "=r"(a) : "l"(p));
    return a;
}

#define CP16(dst, src, sz) \
    asm volatile("cp.async.cg.shared.global [%0], [%1], 16, %2;" \
                 :: "r"(dst), "l"(src), "r"(sz) : "memory")
#define CP_COMMIT() asm volatile("cp.async.commit_group;" ::: "memory")
#define CP_WAIT(n)  asm volatile("cp.async.wait_group %0;" :: "n"(n) : "memory")

__device__ __forceinline__ void ldsm4(uint32_t* r, uint32_t addr) {
    asm volatile("ldmatrix.sync.aligned.m8n8.x4.shared.b16 {%0,%1,%2,%3}, [%4];"
        : "=r"(r[0]), "=r"(r[1]), "=r"(r[2]), "=r"(r[3]) : "r"(addr));
}

__device__ __forceinline__ void mma16816(float* d, const uint32_t* a, const uint32_t* b) {
    asm volatile("mma.sync.aligned.m16n8k16.row.col.f32.f16.f16.f32 "
        "{%0,%1,%2,%3}, {%4,%5,%6,%7}, {%8,%9}, {%0,%1,%2,%3};"
        : "+f"(d[0]), "+f"(d[1]), "+f"(d[2]), "+f"(d[3])
        : "r"(a[0]), "r"(a[1]), "r"(a[2]), "r"(a[3]), "r"(b[0]), "r"(b[1]));
}

// ---------------- prologue: transpose x to [n][hw][ci] fp16 ----------------
__global__ void prep_x(const float* __restrict__ x) {
    __shared__ float tile[32][33];
    const int n = blockIdx.z, cb = blockIdx.y, hb = blockIdx.x;
    const int t = threadIdx.x;
    const int tr = t >> 5, tc = t & 31;
    const float* xp = x + ((size_t)(n * CIN + cb * 32)) * HWSZ + hb * 32;
#pragma unroll
    for (int i = 0; i < 4; i++)
        tile[tr + i * 8][tc] = xp[(size_t)(tr + i * 8) * HWSZ + tc];
    __syncthreads();
#pragma unroll
    for (int it = 0; it < 2; it++) {
        const int idx = it * 256 + t;
        const int hwl = idx >> 4, cp = idx & 15;
        const __half h0 = __float2half(tile[cp * 2][hwl]);
        const __half h1 = __float2half(tile[cp * 2 + 1][hwl]);
        const uint32_t hp = (uint32_t)__half_as_ushort(h0) |
                            ((uint32_t)__half_as_ushort(h1) << 16);
        const size_t e = ((size_t)(n * HWSZ + hb * 32 + hwl)) * CIN + cb * 32 + cp * 2;
        *reinterpret_cast<uint32_t*>(&g_Xh[e]) = hp;
    }
}

// ---------------- prologue: pack weights [co][k] fp16, k = rs*128+ci ----------------
__global__ void prep_w(const float* __restrict__ w) {
    const int idx = blockIdx.x * blockDim.x + threadIdx.x;
    if (idx >= COUT * KTOT) return;
    const int co = idx / KTOT;
    const int k  = idx - co * KTOT;
    const int rs = k >> 7;
    const int ci = k & 127;
    g_Wp[idx] = __float2half(w[co * (CIN * 9) + ci * 9 + rs]);
}

// ---------------- main kernel ----------------
__global__ __launch_bounds__(256, 2)
void conv_mma_kernel(const float* __restrict__ bias, float* __restrict__ out) {
    extern __shared__ char smem[];
    const uint32_t sb = s2u(smem);
    const int t = threadIdx.x, lane = t & 31, warp = t >> 5;
    const int bn = blockIdx.x, bm = blockIdx.y;

    // ---- loader roles: 2 threads per 128B row, quad = half-row ----
    const int lrow = t & 127, quad = t >> 7;
    const __half* a_src = g_Wp + (size_t)(bm * BM + lrow) * KTOT + quad * 32;
    uint32_t ldst[4];
#pragma unroll
    for (int c = 0; c < 4; c++)
        ldst[c] = swz((uint32_t)(lrow * 128 + quad * 64 + c * 16));

    const int p    = bn * BN + lrow;
    const int nimg = p / HWSZ;
    const int hw   = p - nimg * HWSZ;
    const int ph   = hw / WW, pw = hw - ph * WW;
    const __half* xbase = g_Xh + (size_t)nimg * HWSZ * CIN;

    auto load_stage = [&](int kt) {
        const uint32_t base = sb + (uint32_t)(kt % STAGES) * STAGE_BYTES;
        const __half* as = a_src + (size_t)kt * BKC;
#pragma unroll
        for (int c = 0; c < 4; c++)
            CP16(base + ldst[c], as + c * 8, 16);
        const int rs = kt >> 1;                    // 64 ch per stage, 128 per rs
        const int r  = rs / 3, s = rs - 3 * (rs / 3);
        const int ih = ph + r - 1, iw = pw + s - 1;
        const bool valid = ((unsigned)ih < HH) && ((unsigned)iw < WW);
        const int sz  = valid ? 16 : 0;
        const int off = valid ? (ih * WW + iw) : 0;
        const __half* bs = xbase + (size_t)off * CIN + (kt & 1) * 64 + quad * 32;
#pragma unroll
        for (int c = 0; c < 4; c++)
            CP16(base + B_OFF + ldst[c], bs + c * 8, sz);
        CP_COMMIT();
    };

    // ---- MMA roles: 8 warps, 4x2 over (M,N); warp tile 32x64 ----
    const int m0 = (warp >> 1) * 32;
    const int n0 = (warp & 1) * 64;
    const int arow_l = lane & 15;
    const int abyte  = lane & 16;
    const int brow_l = ((lane & 16) >> 1) + (lane & 7);
    const int bbyte  = (lane & 8) * 2;

    float acc[2][8][4];
#pragma unroll
    for (int i = 0; i < 2; i++)
#pragma unroll
        for (int j = 0; j < 8; j++)
#pragma unroll
            for (int q = 0; q < 4; q++) acc[i][j][q] = 0.f;

    for (int kt = 0; kt < STAGES - 1; kt++) load_stage(kt);   // 2 groups

#pragma unroll 1
    for (int kt = 0; kt < NST; kt++) {
        CP_WAIT(1);
        __syncthreads();
        if (kt + STAGES - 1 < NST) load_stage(kt + STAGES - 1);
        else                       CP_COMMIT();   // keep group count constant

        const uint32_t base = sb + (uint32_t)(kt % STAGES) * STAGE_BYTES;
#pragma unroll
        for (int ks = 0; ks < 4; ks++) {           // 4 x 16 channels per stage
            uint32_t Ah[2][4];
#pragma unroll
            for (int mi = 0; mi < 2; mi++) {
                const uint32_t rowb = (uint32_t)((m0 + mi * 16 + arow_l) * 128);
                ldsm4(Ah[mi], base + swz(rowb + ks * 32 + abyte));
            }
#pragma unroll
            for (int nj4 = 0; nj4 < 4; nj4++) {
                uint32_t Bh[4];
                const uint32_t rowb = (uint32_t)((n0 + nj4 * 16 + brow_l) * 128);
                ldsm4(Bh, base + B_OFF + swz(rowb + ks * 32 + bbyte));
#pragma unroll
                for (int mi = 0; mi < 2; mi++) {
#pragma unroll
                    for (int half = 0; half < 2; half++)
                        mma16816(acc[mi][nj4 * 2 + half], Ah[mi], &Bh[half * 2]);
                }
            }
        }
    }

    // ---- epilogue: bias + direct STG.64 to NCHW ----
    float bv[2][2];
#pragma unroll
    for (int mi = 0; mi < 2; mi++)
#pragma unroll
        for (int hf = 0; hf < 2; hf++)
            bv[mi][hf] = __ldg(bias + bm * BM + m0 + mi * 16 + (lane >> 2) + hf * 8);

#pragma unroll
    for (int nj = 0; nj < 8; nj++) {
        const int pp  = bn * BN + n0 + nj * 8 + (lane & 3) * 2;
        const int n2  = pp / HWSZ;
        const int hw2 = pp - n2 * HWSZ;
        float* op = out + ((size_t)n2 * COUT + bm * BM) * HWSZ + hw2;
#pragma unroll
        for (int mi = 0; mi < 2; mi++) {
            const int mr = m0 + mi * 16 + (lane >> 2);
            float2 v0 = make_float2(acc[mi][nj][0] + bv[mi][0],
                                    acc[mi][nj][1] + bv[mi][0]);
            float2 v1 = make_float2(acc[mi][nj][2] + bv[mi][1],
                                    acc[mi][nj][3] + bv[mi][1]);
            *reinterpret_cast<float2*>(op + (size_t)mr * HWSZ)       = v0;
            *reinterpret_cast<float2*>(op + (size_t)(mr + 8) * HWSZ) = v1;
        }
    }
}

extern "C" void kernel_launch(void* const* d_in, const int* in_sizes, int n_in,
                              void* d_out, int out_size) {
    const float* x    = (const float*)d_in[0];
    const float* wgt  = (const float*)d_in[1];
    const float* bias = (const float*)d_in[2];
    float* out        = (float*)d_out;

    cudaFuncSetAttribute(conv_mma_kernel,
                         cudaFuncAttributeMaxDynamicSharedMemorySize, SMEM_TOTAL);

    prep_x<<<dim3(HWSZ / 32, CIN / 32, NB), 256>>>(x);
    prep_w<<<(COUT * KTOT + 255) / 256, 256>>>(wgt);

    dim3 grid(PTOT / BN, COUT / BM);   // (784, 2)
    conv_mma_kernel<<<grid, 256, SMEM_TOTAL>>>(bias, out);
}

// round 16
// speedup vs baseline: 4.6932x; 1.0041x over previous
#include <cuda_runtime.h>
#include <cuda_fp16.h>
#include <cstdint>

// ---------------- problem constants ----------------
#define NB    32
#define CIN   128
#define COUT  256
#define HH    56
#define WW    56
#define HWSZ  3136
#define PTOT  100352
#define KTOT  1152

// ---------------- tiling ----------------
#define BM 128          // cout per CTA
#define BN 128          // pixels per CTA
#define BKC 64          // channels per stage (fp16, 128B rows)
#define NST 18          // 1152/64
#define STAGES 3
#define STAGE_BYTES 32768           // A 16KB + B 16KB
#define B_OFF 16384
#define SMEM_TOTAL (STAGES*STAGE_BYTES)   // 98304 -> 2 CTAs/SM

// ---------------- scratch ----------------
__device__ __half g_Xh[(size_t)NB * HWSZ * CIN];        // x transposed [n][hw][ci], fp16
__device__ __half g_Wp[(size_t)COUT * KTOT];            // w packed [co][k], fp16

__device__ __forceinline__ uint32_t swz(uint32_t o) { return o ^ ((o >> 3) & 0x70); }

__device__ __forceinline__ uint32_t s2u(const void* p) {
    uint32_t a;
    asm("{ .reg .u64 t; cvta.to.shared.u64 t, %1; cvt.u32.u64 %0, t; }" : "=r"(a) : "l"(p));
    return a;
}

#define CP16(dst, src, sz) \
    asm volatile("cp.async.cg.shared.global [%0], [%1], 16, %2;" \
                 :: "r"(dst), "l"(src), "r"(sz) : "memory")
#define CP_COMMIT() asm volatile("cp.async.commit_group;" ::: "memory")
#define CP_WAIT(n)  asm volatile("cp.async.wait_group %0;" :: "n"(n) : "memory")

__device__ __forceinline__ void ldsm4(uint32_t* r, uint32_t addr) {
    asm volatile("ldmatrix.sync.aligned.m8n8.x4.shared.b16 {%0,%1,%2,%3}, [%4];"
        : "=r"(r[0]), "=r"(r[1]), "=r"(r[2]), "=r"(r[3]) : "r"(addr));
}

__device__ __forceinline__ void mma16816(float* d, const uint32_t* a, const uint32_t* b) {
    asm volatile("mma.sync.aligned.m16n8k16.row.col.f32.f16.f16.f32 "
        "{%0,%1,%2,%3}, {%4,%5,%6,%7}, {%8,%9}, {%0,%1,%2,%3};"
        : "+f"(d[0]), "+f"(d[1]), "+f"(d[2]), "+f"(d[3])
        : "r"(a[0]), "r"(a[1]), "r"(a[2]), "r"(a[3]), "r"(b[0]), "r"(b[1]));
}

// ---------------- prologue: transpose x to [n][hw][ci] fp16 ----------------
__global__ void prep_x(const float* __restrict__ x) {
    __shared__ float tile[32][33];
    const int n = blockIdx.z, cb = blockIdx.y, hb = blockIdx.x;
    const int t = threadIdx.x;
    const int tr = t >> 5, tc = t & 31;
    const float* xp = x + ((size_t)(n * CIN + cb * 32)) * HWSZ + hb * 32;
#pragma unroll
    for (int i = 0; i < 4; i++)
        tile[tr + i * 8][tc] = xp[(size_t)(tr + i * 8) * HWSZ + tc];
    __syncthreads();
#pragma unroll
    for (int it = 0; it < 2; it++) {
        const int idx = it * 256 + t;
        const int hwl = idx >> 4, cp = idx & 15;
        const __half h0 = __float2half(tile[cp * 2][hwl]);
        const __half h1 = __float2half(tile[cp * 2 + 1][hwl]);
        const uint32_t hp = (uint32_t)__half_as_ushort(h0) |
                            ((uint32_t)__half_as_ushort(h1) << 16);
        const size_t e = ((size_t)(n * HWSZ + hb * 32 + hwl)) * CIN + cb * 32 + cp * 2;
        *reinterpret_cast<uint32_t*>(&g_Xh[e]) = hp;
    }
}

// ---------------- prologue: pack weights [co][k] fp16, k = rs*128+ci ----------------
__global__ void prep_w(const float* __restrict__ w) {
    const int idx = blockIdx.x * blockDim.x + threadIdx.x;
    if (idx >= COUT * KTOT) return;
    const int co = idx / KTOT;
    const int k  = idx - co * KTOT;
    const int rs = k >> 7;
    const int ci = k & 127;
    g_Wp[idx] = __float2half(w[co * (CIN * 9) + ci * 9 + rs]);
}

// ---------------- main kernel ----------------
__global__ __launch_bounds__(256, 2)
void conv_mma_kernel(const float* __restrict__ bias, float* __restrict__ out) {
    extern __shared__ char smem[];
    const uint32_t sb = s2u(smem);
    const int t = threadIdx.x, lane = t & 31, warp = t >> 5;
    const int bm = blockIdx.x, bn = blockIdx.y;   // bm fastest: B-tile L2 reuse

    // ---- loader roles: 2 threads per 128B row, quad = half-row ----
    const int lrow = t & 127, quad = t >> 7;
    const __half* a_src = g_Wp + (size_t)(bm * BM + lrow) * KTOT + quad * 32;
    uint32_t ldst[4];
#pragma unroll
    for (int c = 0; c < 4; c++)
        ldst[c] = swz((uint32_t)(lrow * 128 + quad * 64 + c * 16));

    const int p    = bn * BN + lrow;
    const int nimg = p / HWSZ;
    const int hw   = p - nimg * HWSZ;
    const int ph   = hw / WW, pw = hw - ph * WW;
    const __half* xbase = g_Xh + (size_t)nimg * HWSZ * CIN;

    auto load_stage = [&](int kt) {
        const uint32_t base = sb + (uint32_t)(kt % STAGES) * STAGE_BYTES;
        const __half* as = a_src + (size_t)kt * BKC;
#pragma unroll
        for (int c = 0; c < 4; c++)
            CP16(base + ldst[c], as + c * 8, 16);
        const int rs = kt >> 1;
        const int r  = rs / 3, s = rs - 3 * (rs / 3);
        const int ih = ph + r - 1, iw = pw + s - 1;
        const bool valid = ((unsigned)ih < HH) && ((unsigned)iw < WW);
        const int sz  = valid ? 16 : 0;
        const int off = valid ? (ih * WW + iw) : 0;
        const __half* bs = xbase + (size_t)off * CIN + (kt & 1) * 64 + quad * 32;
#pragma unroll
        for (int c = 0; c < 4; c++)
            CP16(base + B_OFF + ldst[c], bs + c * 8, sz);
        CP_COMMIT();
    };

    // ---- MMA roles: 8 warps, 4x2 over (M,N); warp tile 32x64 ----
    const int m0 = (warp >> 1) * 32;
    const int n0 = (warp & 1) * 64;
    const int arow_l = lane & 15;
    const int abyte  = lane & 16;
    const int brow_l = ((lane & 16) >> 1) + (lane & 7);
    const int bbyte  = (lane & 8) * 2;

    float acc[2][8][4];
#pragma unroll
    for (int i = 0; i < 2; i++)
#pragma unroll
        for (int j = 0; j < 8; j++)
#pragma unroll
            for (int q = 0; q < 4; q++) acc[i][j][q] = 0.f;

    for (int kt = 0; kt < STAGES - 1; kt++) load_stage(kt);   // 2 groups

#pragma unroll 1
    for (int kt = 0; kt < NST; kt++) {
        CP_WAIT(1);
        __syncthreads();
        if (kt + STAGES - 1 < NST) load_stage(kt + STAGES - 1);
        else                       CP_COMMIT();   // keep group count constant

        const uint32_t base = sb + (uint32_t)(kt % STAGES) * STAGE_BYTES;
#pragma unroll
        for (int ks = 0; ks < 4; ks++) {           // 4 x 16 channels per stage
            // ---- batch all fragment loads for this ks before any MMA ----
            uint32_t Ah[2][4], Bh[4][4];
#pragma unroll
            for (int mi = 0; mi < 2; mi++) {
                const uint32_t rowb = (uint32_t)((m0 + mi * 16 + arow_l) * 128);
                ldsm4(Ah[mi], base + swz(rowb + ks * 32 + abyte));
            }
#pragma unroll
            for (int nj4 = 0; nj4 < 4; nj4++) {
                const uint32_t rowb = (uint32_t)((n0 + nj4 * 16 + brow_l) * 128);
                ldsm4(Bh[nj4], base + B_OFF + swz(rowb + ks * 32 + bbyte));
            }
            // ---- 16 MMAs ----
#pragma unroll
            for (int nj4 = 0; nj4 < 4; nj4++) {
#pragma unroll
                for (int mi = 0; mi < 2; mi++) {
#pragma unroll
                    for (int half = 0; half < 2; half++)
                        mma16816(acc[mi][nj4 * 2 + half], Ah[mi], &Bh[nj4][half * 2]);
                }
            }
        }
    }

    // ---- epilogue: bias + direct STG.64 to NCHW ----
    float bv[2][2];
#pragma unroll
    for (int mi = 0; mi < 2; mi++)
#pragma unroll
        for (int hf = 0; hf < 2; hf++)
            bv[mi][hf] = __ldg(bias + bm * BM + m0 + mi * 16 + (lane >> 2) + hf * 8);

#pragma unroll
    for (int nj = 0; nj < 8; nj++) {
        const int pp  = bn * BN + n0 + nj * 8 + (lane & 3) * 2;
        const int n2  = pp / HWSZ;
        const int hw2 = pp - n2 * HWSZ;
        float* op = out + ((size_t)n2 * COUT + bm * BM) * HWSZ + hw2;
#pragma unroll
        for (int mi = 0; mi < 2; mi++) {
            const int mr = m0 + mi * 16 + (lane >> 2);
            float2 v0 = make_float2(acc[mi][nj][0] + bv[mi][0],
                                    acc[mi][nj][1] + bv[mi][0]);
            float2 v1 = make_float2(acc[mi][nj][2] + bv[mi][1],
                                    acc[mi][nj][3] + bv[mi][1]);
            *reinterpret_cast<float2*>(op + (size_t)mr * HWSZ)       = v0;
            *reinterpret_cast<float2*>(op + (size_t)(mr + 8) * HWSZ) = v1;
        }
    }
}

extern "C" void kernel_launch(void* const* d_in, const int* in_sizes, int n_in,
                              void* d_out, int out_size) {
    const float* x    = (const float*)d_in[0];
    const float* wgt  = (const float*)d_in[1];
    const float* bias = (const float*)d_in[2];
    float* out        = (float*)d_out;

    cudaFuncSetAttribute(conv_mma_kernel,
                         cudaFuncAttributeMaxDynamicSharedMemorySize, SMEM_TOTAL);

    prep_x<<<dim3(HWSZ / 32, CIN / 32, NB), 256>>>(x);
    prep_w<<<(COUT * KTOT + 255) / 256, 256>>>(wgt);

    dim3 grid(COUT / BM, PTOT / BN);   // (2, 784) — bm fastest
    conv_mma_kernel<<<grid, 256, SMEM_TOTAL>>>(bias, out);
}